// round 1
// baseline (speedup 1.0000x reference)
#include <cuda_runtime.h>
#include <cstdint>
#include <cstddef>

// Problem dims
#define Hd    512
#define Bn    64
#define OBSn  256
#define FUTn  256
#define Tn    512
#define G4    2048
#define BT    32768          // Bn*Tn
#define BF    16384          // Bn*FUTn
#define OUT1  16777216       // Bn*Tn*Hd

// ---------------- scratch (no allocation allowed; device globals) -------------
__device__ float d_XG[(size_t)BF * G4];        // x-gates, reused for attention scores
__device__ float d_LH[(size_t)BT * Hd];        // lstm_hidden (concat observed + lstm h)
__device__ float d_A1[(size_t)BT * Hd];
__device__ float d_A2[(size_t)BT * Hd];
__device__ float d_Qb[(size_t)BT * Hd];
__device__ float d_Kb[(size_t)BT * Hd];
__device__ float d_Vb[(size_t)BT * Hd];
__device__ float d_Cc[2][(size_t)Bn * Hd];     // LSTM cell double buffer

__device__ __forceinline__ float sigmoidf_(float x) { return 1.0f / (1.0f + expf(-x)); }

// ======================= TN GEMM: C = A[M,K] @ W[N,K]^T + b1 + b2 =============
// 128x128 tile, BK=8, 256 threads, 8x8 microtile. M,N multiples of 128, K of 8.
__global__ __launch_bounds__(256) void gemm_tn(
    const float* __restrict__ A, const float* __restrict__ W,
    const float* __restrict__ b1, const float* __restrict__ b2,
    float* __restrict__ C, int M, int N, int K)
{
    __shared__ float As[8][132];
    __shared__ float Ws[8][132];
    const int m0 = blockIdx.y * 128, n0 = blockIdx.x * 128;
    const int t  = threadIdx.x;
    const int tx = t & 15, ty = t >> 4;
    const int lr = t >> 1, lk = (t & 1) * 4;

    float acc[8][8];
#pragma unroll
    for (int i = 0; i < 8; i++)
#pragma unroll
        for (int j = 0; j < 8; j++) acc[i][j] = 0.0f;

    const float* Ap = A + (size_t)(m0 + lr) * K + lk;
    const float* Wp = W + (size_t)(n0 + lr) * K + lk;

    for (int k0 = 0; k0 < K; k0 += 8) {
        float4 a4 = *(const float4*)(Ap + k0);
        float4 w4 = *(const float4*)(Wp + k0);
        As[lk + 0][lr] = a4.x; As[lk + 1][lr] = a4.y; As[lk + 2][lr] = a4.z; As[lk + 3][lr] = a4.w;
        Ws[lk + 0][lr] = w4.x; Ws[lk + 1][lr] = w4.y; Ws[lk + 2][lr] = w4.z; Ws[lk + 3][lr] = w4.w;
        __syncthreads();
#pragma unroll
        for (int k = 0; k < 8; k++) {
            float4 A0 = *(const float4*)&As[k][ty * 8];
            float4 A1v = *(const float4*)&As[k][ty * 8 + 4];
            float4 W0 = *(const float4*)&Ws[k][tx * 8];
            float4 W1v = *(const float4*)&Ws[k][tx * 8 + 4];
            float ar[8] = {A0.x, A0.y, A0.z, A0.w, A1v.x, A1v.y, A1v.z, A1v.w};
            float wr[8] = {W0.x, W0.y, W0.z, W0.w, W1v.x, W1v.y, W1v.z, W1v.w};
#pragma unroll
            for (int i = 0; i < 8; i++)
#pragma unroll
                for (int j = 0; j < 8; j++) acc[i][j] += ar[i] * wr[j];
        }
        __syncthreads();
    }

    float bb[8];
#pragma unroll
    for (int j = 0; j < 8; j++) {
        int n = n0 + tx * 8 + j;
        float v = b1 ? b1[n] : 0.0f;
        if (b2) v += b2[n];
        bb[j] = v;
    }
#pragma unroll
    for (int i = 0; i < 8; i++) {
        size_t row = (size_t)(m0 + ty * 8 + i) * N + n0 + tx * 8;
        float4 o0, o1;
        o0.x = acc[i][0] + bb[0]; o0.y = acc[i][1] + bb[1];
        o0.z = acc[i][2] + bb[2]; o0.w = acc[i][3] + bb[3];
        o1.x = acc[i][4] + bb[4]; o1.y = acc[i][5] + bb[5];
        o1.z = acc[i][6] + bb[6]; o1.w = acc[i][7] + bb[7];
        *(float4*)&C[row]     = o0;
        *(float4*)&C[row + 4] = o1;
    }
}

// ============== batched scores: S = scale * Q Kt^T with causal mask ===========
// per batch M=N=K=512, batch stride 512*512. blockIdx.z = batch.
__global__ __launch_bounds__(256) void gemm_tn_scores(
    const float* __restrict__ Qm, const float* __restrict__ Km,
    float* __restrict__ C, float scale)
{
    __shared__ float As[8][132];
    __shared__ float Ws[8][132];
    const size_t bo = (size_t)blockIdx.z * 262144;
    const float* A = Qm + bo;
    const float* W = Km + bo;
    float* Cb = C + bo;
    const int m0 = blockIdx.y * 128, n0 = blockIdx.x * 128;
    const int t = threadIdx.x;
    const int tx = t & 15, ty = t >> 4;
    const int lr = t >> 1, lk = (t & 1) * 4;

    float acc[8][8];
#pragma unroll
    for (int i = 0; i < 8; i++)
#pragma unroll
        for (int j = 0; j < 8; j++) acc[i][j] = 0.0f;

    const float* Ap = A + (size_t)(m0 + lr) * 512 + lk;
    const float* Wp = W + (size_t)(n0 + lr) * 512 + lk;

    for (int k0 = 0; k0 < 512; k0 += 8) {
        float4 a4 = *(const float4*)(Ap + k0);
        float4 w4 = *(const float4*)(Wp + k0);
        As[lk + 0][lr] = a4.x; As[lk + 1][lr] = a4.y; As[lk + 2][lr] = a4.z; As[lk + 3][lr] = a4.w;
        Ws[lk + 0][lr] = w4.x; Ws[lk + 1][lr] = w4.y; Ws[lk + 2][lr] = w4.z; Ws[lk + 3][lr] = w4.w;
        __syncthreads();
#pragma unroll
        for (int k = 0; k < 8; k++) {
            float4 A0 = *(const float4*)&As[k][ty * 8];
            float4 A1v = *(const float4*)&As[k][ty * 8 + 4];
            float4 W0 = *(const float4*)&Ws[k][tx * 8];
            float4 W1v = *(const float4*)&Ws[k][tx * 8 + 4];
            float ar[8] = {A0.x, A0.y, A0.z, A0.w, A1v.x, A1v.y, A1v.z, A1v.w};
            float wr[8] = {W0.x, W0.y, W0.z, W0.w, W1v.x, W1v.y, W1v.z, W1v.w};
#pragma unroll
            for (int i = 0; i < 8; i++)
#pragma unroll
                for (int j = 0; j < 8; j++) acc[i][j] += ar[i] * wr[j];
        }
        __syncthreads();
    }
#pragma unroll
    for (int i = 0; i < 8; i++) {
        int q = m0 + ty * 8 + i;
#pragma unroll
        for (int j = 0; j < 8; j++) {
            int kk = n0 + tx * 8 + j;
            float v = acc[i][j] * scale;
            if (kk > q) v = -1e30f;
            Cb[(size_t)q * 512 + kk] = v;
        }
    }
}

// ==================== batched NN GEMM: O = attn[512,512] @ V[512,512] =========
__global__ __launch_bounds__(256) void gemm_nn_b(
    const float* __restrict__ Am, const float* __restrict__ Bm, float* __restrict__ C)
{
    __shared__ float As[8][132];
    __shared__ float Bs[8][128];
    const size_t bo = (size_t)blockIdx.z * 262144;
    const float* A = Am + bo;
    const float* B = Bm + bo;
    float* Cb = C + bo;
    const int m0 = blockIdx.y * 128, n0 = blockIdx.x * 128;
    const int t = threadIdx.x;
    const int tx = t & 15, ty = t >> 4;
    const int lr = t >> 1, lk = (t & 1) * 4;   // A-tile loads
    const int kr = t >> 5, nq = t & 31;        // B-tile loads

    float acc[8][8];
#pragma unroll
    for (int i = 0; i < 8; i++)
#pragma unroll
        for (int j = 0; j < 8; j++) acc[i][j] = 0.0f;

    const float* Ap = A + (size_t)(m0 + lr) * 512 + lk;

    for (int k0 = 0; k0 < 512; k0 += 8) {
        float4 a4 = *(const float4*)(Ap + k0);
        float4 b4 = *(const float4*)(B + (size_t)(k0 + kr) * 512 + n0 + nq * 4);
        As[lk + 0][lr] = a4.x; As[lk + 1][lr] = a4.y; As[lk + 2][lr] = a4.z; As[lk + 3][lr] = a4.w;
        *(float4*)&Bs[kr][nq * 4] = b4;
        __syncthreads();
#pragma unroll
        for (int k = 0; k < 8; k++) {
            float4 A0 = *(const float4*)&As[k][ty * 8];
            float4 A1v = *(const float4*)&As[k][ty * 8 + 4];
            float4 W0 = *(const float4*)&Bs[k][tx * 8];
            float4 W1v = *(const float4*)&Bs[k][tx * 8 + 4];
            float ar[8] = {A0.x, A0.y, A0.z, A0.w, A1v.x, A1v.y, A1v.z, A1v.w};
            float wr[8] = {W0.x, W0.y, W0.z, W0.w, W1v.x, W1v.y, W1v.z, W1v.w};
#pragma unroll
            for (int i = 0; i < 8; i++)
#pragma unroll
                for (int j = 0; j < 8; j++) acc[i][j] += ar[i] * wr[j];
        }
        __syncthreads();
    }
#pragma unroll
    for (int i = 0; i < 8; i++) {
        size_t row = (size_t)(m0 + ty * 8 + i) * 512 + n0 + tx * 8;
        float4 o0, o1;
        o0.x = acc[i][0]; o0.y = acc[i][1]; o0.z = acc[i][2]; o0.w = acc[i][3];
        o1.x = acc[i][4]; o1.y = acc[i][5]; o1.z = acc[i][6]; o1.w = acc[i][7];
        *(float4*)&Cb[row]     = o0;
        *(float4*)&Cb[row + 4] = o1;
    }
}

// ======================= copy observed rows into lstm_hidden ==================
__global__ void copy_obs_k(const float* __restrict__ obs, float* __restrict__ LH)
{
    size_t i = (size_t)blockIdx.x * blockDim.x + threadIdx.x;
    if (i < (size_t)Bn * OBSn * Hd) {
        size_t b = i >> 17;            // / (256*512)
        size_t rem = i & 131071;
        LH[b * 262144 + rem] = obs[i]; // first 256 time rows per batch are contiguous
    }
}

// ============================ one LSTM step ===================================
// grid (16 unit-tiles of 32, 8 batch-tiles of 8), 256 threads
__global__ __launch_bounds__(256) void lstm_step(
    const float* __restrict__ hprev, long hstride,
    const float* __restrict__ cprev, long cstride,
    float* __restrict__ cnext,            // [Bn*Hd], stride Hd
    float* __restrict__ hout,             // base LH + (256+t)*512, batch stride 262144
    const float* __restrict__ xg,         // base XG + t*2048, batch stride 524288
    const float* __restrict__ Whh)        // [2048,512]
{
    __shared__ float Hs[32][9];
    __shared__ float Ws[32][132];
    __shared__ float gsm[8][128];
    const int u0 = blockIdx.x * 32;
    const int m0 = blockIdx.y * 8;
    const int t = threadIdx.x;
    const int tx = t & 127, ty = t >> 7;
    const int wr = t >> 3;          // 0..31
    const int wk = (t & 7) * 4;     // 0..28

    float acc[4] = {0.f, 0.f, 0.f, 0.f};

    for (int k0 = 0; k0 < 512; k0 += 32) {
        Hs[t & 31][t >> 5] = hprev[(size_t)(m0 + (t >> 5)) * hstride + k0 + (t & 31)];
#pragma unroll
        for (int sub = 0; sub < 4; sub++) {
            int grow = sub * 512 + u0 + wr;
            float4 w4 = *(const float4*)(Whh + (size_t)grow * 512 + k0 + wk);
            int r = sub * 32 + wr;
            Ws[wk + 0][r] = w4.x; Ws[wk + 1][r] = w4.y; Ws[wk + 2][r] = w4.z; Ws[wk + 3][r] = w4.w;
        }
        __syncthreads();
#pragma unroll
        for (int k = 0; k < 32; k++) {
            float w = Ws[k][tx];
#pragma unroll
            for (int i = 0; i < 4; i++) acc[i] += Hs[k][ty * 4 + i] * w;
        }
        __syncthreads();
    }
#pragma unroll
    for (int i = 0; i < 4; i++) gsm[ty * 4 + i][tx] = acc[i];
    __syncthreads();

    {
        int m = t >> 5, uu = t & 31;
        const float* xrow = xg + (size_t)(m0 + m) * 524288;
        float gi = gsm[m][uu]       + xrow[0 * 512 + u0 + uu];
        float gf = gsm[m][32 + uu]  + xrow[1 * 512 + u0 + uu];
        float gg = gsm[m][64 + uu]  + xrow[2 * 512 + u0 + uu];
        float go = gsm[m][96 + uu]  + xrow[3 * 512 + u0 + uu];
        float c  = cprev[(size_t)(m0 + m) * cstride + u0 + uu];
        float cn = sigmoidf_(gf) * c + sigmoidf_(gi) * tanhf(gg);
        float hn = sigmoidf_(go) * tanhf(cn);
        cnext[(size_t)(m0 + m) * Hd + u0 + uu] = cn;
        hout[(size_t)(m0 + m) * 262144 + u0 + uu] = hn;
    }
}

// ====================== fused GLU + LayerNorm (one block/row) =================
__global__ __launch_bounds__(256) void gluln_k(
    const float* __restrict__ a1, const float* __restrict__ a2,
    const float* __restrict__ y1, const float* __restrict__ y2,
    const float* __restrict__ gamma, const float* __restrict__ beta,
    float* __restrict__ outp, int splitY)
{
    __shared__ float red[8];
    const int r = blockIdx.x;
    const int t = threadIdx.x;
    const float* yp;
    if (splitY) {
        int b = r >> 9, tt = r & 511;
        yp = (tt < 256) ? (y1 + ((size_t)(b * 256 + tt)) * 512)
                        : (y2 + ((size_t)(b * 256 + tt - 256)) * 512);
    } else {
        yp = y1 + (size_t)r * 512;
    }
    const float* p1 = a1 + (size_t)r * 512;
    const float* p2 = a2 + (size_t)r * 512;
    float z0 = sigmoidf_(p1[t])       * p2[t]       + yp[t];
    float z1 = sigmoidf_(p1[t + 256]) * p2[t + 256] + yp[t + 256];

    // mean
    float s = z0 + z1;
#pragma unroll
    for (int o = 16; o > 0; o >>= 1) s += __shfl_xor_sync(0xffffffffu, s, o);
    if ((t & 31) == 0) red[t >> 5] = s;
    __syncthreads();
    if (t < 32) {
        float a = (t < 8) ? red[t] : 0.0f;
#pragma unroll
        for (int o = 4; o > 0; o >>= 1) a += __shfl_xor_sync(0xffffffffu, a, o);
        if (t == 0) red[0] = a;
    }
    __syncthreads();
    float mu = red[0] * (1.0f / 512.0f);
    float d0 = z0 - mu, d1 = z1 - mu;
    float s2 = d0 * d0 + d1 * d1;
    __syncthreads();   // protect red[] reuse
#pragma unroll
    for (int o = 16; o > 0; o >>= 1) s2 += __shfl_xor_sync(0xffffffffu, s2, o);
    if ((t & 31) == 0) red[t >> 5] = s2;
    __syncthreads();
    if (t < 32) {
        float a = (t < 8) ? red[t] : 0.0f;
#pragma unroll
        for (int o = 4; o > 0; o >>= 1) a += __shfl_xor_sync(0xffffffffu, a, o);
        if (t == 0) red[0] = a;
    }
    __syncthreads();
    float inv = rsqrtf(red[0] * (1.0f / 512.0f) + 1e-5f);
    outp[(size_t)r * 512 + t]       = gamma[t]       * d0 * inv + beta[t];
    outp[(size_t)r * 512 + t + 256] = gamma[t + 256] * d1 * inv + beta[t + 256];
}

// ========================= row softmax over 512 cols ==========================
__global__ __launch_bounds__(256) void softmax_k(
    const float* __restrict__ S, float* __restrict__ A)
{
    __shared__ float red[8];
    const int r = blockIdx.x;
    const int t = threadIdx.x;
    const float* p = S + (size_t)r * 512;
    float v0 = p[t], v1 = p[t + 256];
    float m = fmaxf(v0, v1);
#pragma unroll
    for (int o = 16; o > 0; o >>= 1) m = fmaxf(m, __shfl_xor_sync(0xffffffffu, m, o));
    if ((t & 31) == 0) red[t >> 5] = m;
    __syncthreads();
    if (t < 32) {
        float a = (t < 8) ? red[t] : -3.4e38f;
#pragma unroll
        for (int o = 4; o > 0; o >>= 1) a = fmaxf(a, __shfl_xor_sync(0xffffffffu, a, o));
        if (t == 0) red[0] = a;
    }
    __syncthreads();
    float mx = red[0];
    float e0 = expf(v0 - mx), e1 = expf(v1 - mx);
    float s = e0 + e1;
    __syncthreads();
#pragma unroll
    for (int o = 16; o > 0; o >>= 1) s += __shfl_xor_sync(0xffffffffu, s, o);
    if ((t & 31) == 0) red[t >> 5] = s;
    __syncthreads();
    if (t < 32) {
        float a = (t < 8) ? red[t] : 0.0f;
#pragma unroll
        for (int o = 4; o > 0; o >>= 1) a += __shfl_xor_sync(0xffffffffu, a, o);
        if (t == 0) red[0] = a;
    }
    __syncthreads();
    float inv = 1.0f / red[0];
    A[(size_t)r * 512 + t]       = e0 * inv;
    A[(size_t)r * 512 + t + 256] = e1 * inv;
}

// ================================= host =======================================
extern "C" void kernel_launch(void* const* d_in, const int* in_sizes, int n_in,
                              void* d_out, int out_size)
{
    const float* obs   = (const float*)d_in[0];
    const float* fut   = (const float*)d_in[1];
    const float* W_ih  = (const float*)d_in[2];
    const float* W_hh  = (const float*)d_in[3];
    const float* b_ih  = (const float*)d_in[4];
    const float* b_hh  = (const float*)d_in[5];
    const float* g1W1  = (const float*)d_in[6];
    const float* g1b1  = (const float*)d_in[7];
    const float* g1W2  = (const float*)d_in[8];
    const float* g1b2  = (const float*)d_in[9];
    const float* g1g   = (const float*)d_in[10];
    const float* g1b   = (const float*)d_in[11];
    const float* Wq    = (const float*)d_in[12];
    const float* bq    = (const float*)d_in[13];
    const float* Wk    = (const float*)d_in[14];
    const float* bk    = (const float*)d_in[15];
    const float* Wv    = (const float*)d_in[16];
    const float* bv    = (const float*)d_in[17];
    const float* Wo    = (const float*)d_in[18];
    const float* bo    = (const float*)d_in[19];
    const float* g2W1  = (const float*)d_in[20];
    const float* g2b1  = (const float*)d_in[21];
    const float* g2W2  = (const float*)d_in[22];
    const float* g2b2  = (const float*)d_in[23];
    const float* g2g   = (const float*)d_in[24];
    const float* g2b   = (const float*)d_in[25];

    float* out       = (float*)d_out;
    float* glu_delta = out;
    float* glu_phi   = out + (size_t)OUT1;
    float* attn      = out + (size_t)2 * OUT1;

    float *XG, *LH, *A1, *A2, *Qb, *Kb, *Vb, *Cc;
    cudaGetSymbolAddress((void**)&XG, d_XG);
    cudaGetSymbolAddress((void**)&LH, d_LH);
    cudaGetSymbolAddress((void**)&A1, d_A1);
    cudaGetSymbolAddress((void**)&A2, d_A2);
    cudaGetSymbolAddress((void**)&Qb, d_Qb);
    cudaGetSymbolAddress((void**)&Kb, d_Kb);
    cudaGetSymbolAddress((void**)&Vb, d_Vb);
    cudaGetSymbolAddress((void**)&Cc, d_Cc);
    float* C0 = Cc;
    float* C1 = Cc + (size_t)Bn * Hd;

    // 1. X_gates = fut @ W_ih^T + (b_ih + b_hh)
    gemm_tn<<<dim3(G4 / 128, BF / 128), 256>>>(fut, W_ih, b_ih, b_hh, XG, BF, G4, Hd);

    // 2. lstm_hidden[:, :256, :] = vsn_observed
    copy_obs_k<<<(Bn * OBSn * Hd + 255) / 256, 256>>>(obs, LH);

    // 3. sequential LSTM (h0 = c0 = obs[:, -1, :])
    for (int s = 0; s < 256; s++) {
        const float* hp = (s == 0) ? (obs + (size_t)255 * 512) : (LH + (size_t)(255 + s) * 512);
        long hs = (s == 0) ? 131072 : 262144;
        const float* cp = (s == 0) ? (obs + (size_t)255 * 512) : ((s & 1) ? C0 : C1);
        long cs = (s == 0) ? 131072 : 512;
        float* cn = (s & 1) ? C1 : C0;
        lstm_step<<<dim3(16, 8), 256>>>(hp, hs, cp, cs, cn,
                                        LH + (size_t)(256 + s) * 512,
                                        XG + (size_t)s * G4, W_hh);
    }

    // 4. GLU-LN #1 -> glu_phi
    gemm_tn<<<dim3(4, 256), 256>>>(LH, g1W1, g1b1, nullptr, A1, BT, Hd, Hd);
    gemm_tn<<<dim3(4, 256), 256>>>(LH, g1W2, g1b2, nullptr, A2, BT, Hd, Hd);
    gluln_k<<<BT, 256>>>(A1, A2, obs, fut, g1g, g1b, glu_phi, 1);

    // 5. QKV
    gemm_tn<<<dim3(4, 256), 256>>>(glu_phi, Wq, bq, nullptr, Qb, BT, Hd, Hd);
    gemm_tn<<<dim3(4, 256), 256>>>(glu_phi, Wk, bk, nullptr, Kb, BT, Hd, Hd);
    gemm_tn<<<dim3(4, 256), 256>>>(glu_phi, Wv, bv, nullptr, Vb, BT, Hd, Hd);

    // 6. scores (reuse XG) + softmax -> attn output
    gemm_tn_scores<<<dim3(4, 4, 64), 256>>>(Qb, Kb, XG, 0.04419417382415922f);
    softmax_k<<<BT, 256>>>(XG, attn);

    // 7. attn @ V -> reuse Qb; projection -> reuse Kb
    gemm_nn_b<<<dim3(4, 4, 64), 256>>>(attn, Vb, Qb);
    gemm_tn<<<dim3(4, 256), 256>>>(Qb, Wo, bo, nullptr, Kb, BT, Hd, Hd);

    // 8. GLU-LN #2 -> glu_delta
    gemm_tn<<<dim3(4, 256), 256>>>(Kb, g2W1, g2b1, nullptr, A1, BT, Hd, Hd);
    gemm_tn<<<dim3(4, 256), 256>>>(Kb, g2W2, g2b2, nullptr, A2, BT, Hd, Hd);
    gluln_k<<<BT, 256>>>(A1, A2, glu_phi, nullptr, g2g, g2b, glu_delta, 0);
}